// round 6
// baseline (speedup 1.0000x reference)
#include <cuda_runtime.h>
#include <cstdint>

#define NN 256
#define MM 65536
#define EE 8192
#define TBL 131072
#define K0 512
#define EMPTYK 0xFFFFFFFFFFFFFFFFull

// ---------------- scratch (static device globals; no allocs) ----------------
__device__ int                d_labels[MM];
__device__ int                d_sortedRC[2 * MM];   // [0,M): sorted rows, [M,2M): sorted cols
__device__ unsigned long long d_hashRC[2 * NN];     // row hashes, col hashes
__device__ unsigned char      d_A[MM];
__device__ int                d_rid[NN], d_cid[NN];
__device__ unsigned long long d_tkey[TBL];
__device__ int                d_tmin[TBL];
__device__ int                d_slot[MM];
__device__ int                d_preL[MM];
__device__ int                d_bsum[NN], d_boff[NN];
__device__ int                d_min0[K0];
__device__ int                d_rank0[K0];
__device__ int                d_hist[3 * MM];       // integer histograms (exact)

// ---------------- helpers ----------------
__device__ __forceinline__ unsigned long long mix64(unsigned long long z) {
    z += 0x9E3779B97F4A7C15ull;
    z = (z ^ (z >> 30)) * 0xBF58476D1CE4E5B9ull;
    z = (z ^ (z >> 27)) * 0x94D049BB133111EBull;
    return z ^ (z >> 31);
}

// ---------------- kernels ----------------

// Zero integer hist scratch, adjacency, key-0 table, big hash table.
__global__ void k_init() {
    int idx = blockIdx.x * 256 + threadIdx.x;           // 768*256 = 196608 threads
    d_hist[idx] = 0;                                    // 3*MM exactly
    if (idx < MM)  d_A[idx] = 0;
    if (idx < K0)  d_min0[idx] = 0x7FFFFFFF;
    if (idx < TBL) { d_tkey[idx] = EMPTYK; d_tmin[idx] = 0x7FFFFFFF; }
}

__global__ void k_edges(const int* ei) {
    int e = blockIdx.x * 256 + threadIdx.x;             // EE threads
    int u = ei[e] & 255, v = ei[EE + e] & 255;
    d_A[u * NN + v] = 1;
}

// Layer-0: min position per (x_i, x_j, A) key under the permutations-then-diagonal order.
__global__ void k_minpos0(const int* x) {
    int m = blockIdx.x * 256 + threadIdx.x;
    int i = m >> 8, j = m & 255;
    int key = ((x[i] & 15) << 5) | ((x[j] & 15) << 1) | (int)d_A[m];
    int pos = (i == j) ? (NN * (NN - 1) + i) : (i * (NN - 1) + (j < i ? j : j - 1));
    if (pos < d_min0[key]) atomicMin(&d_min0[key], pos);
}

// Rank the <=512 layer-0 keys by first-occurrence position.
__global__ void k_rank0() {
    __shared__ int mp[K0];
    int t = threadIdx.x;
    mp[t] = d_min0[t];
    __syncthreads();
    int my = mp[t];
    int r = 0;
    if (my != 0x7FFFFFFF) {
        for (int k = 0; k < K0; k++) r += (mp[k] < my) ? 1 : 0;
    }
    d_rank0[t] = r;
}

__global__ void k_label0(const int* x) {
    int m = blockIdx.x * 256 + threadIdx.x;
    int i = m >> 8, j = m & 255;
    int key = ((x[i] & 15) << 5) | ((x[j] & 15) << 1) | (int)d_A[m];
    int lbl = d_rank0[key];
    d_labels[m] = lbl;
    atomicAdd(&d_hist[lbl], 1);
}

// Sort each row (blocks 0..255) / each column (blocks 256..511) of labels; emit a 64-bit hash.
__global__ void k_sort() {
    __shared__ int s[256];
    __shared__ unsigned long long hs[256];
    int b = blockIdx.x, t = threadIdx.x;
    if (b < NN) s[t] = d_labels[b * NN + t];
    else        s[t] = d_labels[t * NN + (b - NN)];
    __syncthreads();
    // bitonic sort, 256 elems, ascending
    for (int k = 2; k <= 256; k <<= 1) {
        for (int j = k >> 1; j > 0; j >>= 1) {
            int ixj = t ^ j;
            if (ixj > t) {
                int a = s[t], bb = s[ixj];
                bool up = ((t & k) == 0);
                if ((a > bb) == up) { s[t] = bb; s[ixj] = a; }
            }
            __syncthreads();
        }
    }
    int v = s[t];
    d_sortedRC[b * 256 + t] = v;
    // positional hash, XOR-reduced
    hs[t] = mix64(((unsigned long long)(unsigned)v << 16) | (unsigned)t);
    __syncthreads();
    for (int o = 128; o > 0; o >>= 1) {
        if (t < o) hs[t] ^= hs[t + o];
        __syncthreads();
    }
    if (t == 0) d_hashRC[b] = hs[0];
}

// rid[i] = smallest i' with identical sorted row (hash prefilter, exact verify). Same for cols.
__global__ void k_dedupe() {
    int b = blockIdx.x, t = threadIdx.x;
    int row = b & 255;
    int groupbase = (b >> 8) * NN;      // 0 for rows, 256 for cols
    int my = d_sortedRC[b * 256 + t];
    unsigned long long h = d_hashRC[b];
    for (int c = 0; c <= row; c++) {
        int cb = groupbase + c;
        if (d_hashRC[cb] != h) continue;   // uniform across block
        int eq = (d_sortedRC[cb * 256 + t] == my);
        if (__syncthreads_and(eq)) {
            if (t == 0) {
                if (b < NN) d_rid[row] = c;
                else        d_cid[row] = c;
            }
            break;                         // uniform across block
        }
    }
}

__global__ void k_cleartbl() {
    int idx = blockIdx.x * 256 + threadIdx.x;
    d_tkey[idx] = EMPTYK;
    d_tmin[idx] = 0x7FFFFFFF;
}

// Insert packed key (label<<16 | rid<<8 | cid) into hash table; record slot, min row-major pos.
__global__ void k_insert() {
    int m = blockIdx.x * 256 + threadIdx.x;
    int i = m >> 8, j = m & 255;
    unsigned int key = ((unsigned)d_labels[m] << 16) | ((unsigned)d_rid[i] << 8) | (unsigned)d_cid[j];
    unsigned long long k64 = (unsigned long long)key;
    unsigned int h = (key * 2654435761u) >> 15;   // -> [0, 2^17)
    int slot;
    while (true) {
        unsigned long long cur = d_tkey[h];
        if (cur == k64) { slot = (int)h; break; }
        if (cur == EMPTYK) {
            unsigned long long old = atomicCAS(&d_tkey[h], EMPTYK, k64);
            if (old == EMPTYK || old == k64) { slot = (int)h; break; }
        }
        h = (h + 1) & (TBL - 1);
    }
    d_slot[m] = slot;
    if (m < d_tmin[slot]) atomicMin(&d_tmin[slot], m);
}

// Per-block exclusive scan of first-occurrence indicator + block sums.
__global__ void k_scanA() {
    __shared__ int sh[256];
    int b = blockIdx.x, t = threadIdx.x, m = b * 256 + t;
    int f = (d_tmin[d_slot[m]] == m) ? 1 : 0;
    sh[t] = f;
    __syncthreads();
    for (int o = 1; o < 256; o <<= 1) {
        int v = (t >= o) ? sh[t - o] : 0;
        __syncthreads();
        sh[t] += v;
        __syncthreads();
    }
    d_preL[m] = sh[t] - f;          // exclusive
    if (t == 255) d_bsum[b] = sh[t];
}

__global__ void k_scanB() {
    __shared__ int sh[256];
    int t = threadIdx.x;
    int v0 = d_bsum[t];
    sh[t] = v0;
    __syncthreads();
    for (int o = 1; o < 256; o <<= 1) {
        int v = (t >= o) ? sh[t - o] : 0;
        __syncthreads();
        sh[t] += v;
        __syncthreads();
    }
    d_boff[t] = sh[t] - v0;         // exclusive
}

// New label = rank of key = #first-occurrences strictly before its first position.
__global__ void k_final(int layer) {
    int m = blockIdx.x * 256 + threadIdx.x;
    int fp = d_tmin[d_slot[m]];
    int lbl = d_preL[fp] + d_boff[fp >> 8];
    d_labels[m] = lbl;
    atomicAdd(&d_hist[layer * MM + lbl], 1);
}

// Convert exact integer histograms to the output dtype (float32).
// Counts <= 65536 are exactly representable in fp32.
__global__ void k_out(float* out) {
    int idx = blockIdx.x * 256 + threadIdx.x;           // 3*MM threads
    out[idx] = (float)d_hist[idx];
}

// ---------------- launch ----------------
extern "C" void kernel_launch(void* const* d_in, const int* in_sizes, int n_in,
                              void* d_out, int out_size) {
    // Fixed problem instance: N=256, E=8192, C=16.
    // Select x vs edge_index by RELATIVE size only: x is the smaller buffer.
    const int* x;
    const int* ei;
    if (in_sizes[0] <= in_sizes[1]) {
        x  = (const int*)d_in[0];
        ei = (const int*)d_in[1];
    } else {
        ei = (const int*)d_in[0];
        x  = (const int*)d_in[1];
    }
    float* out = (float*)d_out;

    k_init<<<768, 256>>>();
    k_edges<<<EE / 256, 256>>>(ei);
    k_minpos0<<<256, 256>>>(x);
    k_rank0<<<1, K0>>>();
    k_label0<<<256, 256>>>(x);

    for (int layer = 1; layer <= 2; layer++) {
        k_sort<<<512, 256>>>();
        k_dedupe<<<512, 256>>>();
        if (layer == 2) k_cleartbl<<<TBL / 256, 256>>>();
        k_insert<<<256, 256>>>();
        k_scanA<<<256, 256>>>();
        k_scanB<<<1, 256>>>();
        k_final<<<256, 256>>>(layer);
    }
    k_out<<<768, 256>>>(out);
}

// round 7
// speedup vs baseline: 1.5071x; 1.5071x over previous
#include <cuda_runtime.h>
#include <cstdint>

#define NN 256
#define MM 65536
#define EE 8192
#define TBL 131072
#define K0 512
#define EMPTYK 0xFFFFFFFFFFFFFFFFull
#define POSINF 0x7FFFFFFF

// ---------------- scratch (static device globals; no allocs) ----------------
__device__ int                d_labels[MM];
__device__ unsigned long long d_hashRC[2 * NN];     // row multiset hashes, col multiset hashes
__device__ unsigned char      d_A[MM];
__device__ int                d_rid[NN], d_cid[NN];
__device__ unsigned long long d_tkey[TBL];
__device__ int                d_tmin[TBL];
__device__ int                d_slot[MM];
__device__ int                d_preL[MM];
__device__ int                d_bsum[NN], d_boff[NN];
__device__ int                d_min0[K0];
__device__ int                d_rank0[K0];

// ---------------- helpers ----------------
__device__ __forceinline__ unsigned long long mix64(unsigned long long z) {
    z += 0x9E3779B97F4A7C15ull;
    z = (z ^ (z >> 30)) * 0xBF58476D1CE4E5B9ull;
    z = (z ^ (z >> 27)) * 0x94D049BB133111EBull;
    return z ^ (z >> 31);
}

// ---------------- kernels ----------------

// Zero float output (3*MM), adjacency, key-0 table, big hash table.
__global__ void k_init(float* out) {
    int idx = blockIdx.x * 256 + threadIdx.x;           // 768*256 = 196608
    out[idx] = 0.0f;                                    // 3*MM exactly
    if (idx < MM)  d_A[idx] = 0;
    if (idx < K0)  d_min0[idx] = POSINF;
    if (idx < TBL) { d_tkey[idx] = EMPTYK; d_tmin[idx] = POSINF; }
}

__global__ void k_edges(const int* ei) {
    int e = blockIdx.x * 256 + threadIdx.x;             // EE threads
    int u = ei[e] & 255, v = ei[EE + e] & 255;
    d_A[u * NN + v] = 1;
}

// Layer-0: min position per (x_i, x_j, A) key, permutations-then-diagonal order.
__global__ void k_minpos0(const int* x) {
    int m = blockIdx.x * 256 + threadIdx.x;
    int i = m >> 8, j = m & 255;
    int key = ((x[i] & 15) << 5) | ((x[j] & 15) << 1) | (int)d_A[m];
    int pos = (i == j) ? (NN * (NN - 1) + i) : (i * (NN - 1) + (j < i ? j : j - 1));
    if (pos < d_min0[key]) atomicMin(&d_min0[key], pos);
}

// Rank the <=512 layer-0 keys by first-occurrence position. 1024 threads,
// two partial 256-scans per key.
__global__ void k_rank0() {
    __shared__ int mp[K0];
    __shared__ int part[1024];
    int t = threadIdx.x;
    if (t < K0) mp[t] = d_min0[t];
    __syncthreads();
    int k = t & 511, h = t >> 9;
    int my = mp[k];
    int r = 0;
    if (my != POSINF) {
        int base = h << 8;
        #pragma unroll 8
        for (int c = 0; c < 256; c++) r += (mp[base + c] < my) ? 1 : 0;
    }
    part[t] = r;
    __syncthreads();
    if (t < K0) d_rank0[t] = part[t] + part[t + 512];
}

__global__ void k_label0(const int* x, float* out) {
    int m = blockIdx.x * 256 + threadIdx.x;
    int i = m >> 8, j = m & 255;
    int key = ((x[i] & 15) << 5) | ((x[j] & 15) << 1) | (int)d_A[m];
    int lbl = d_rank0[key];
    d_labels[m] = lbl;
    atomicAdd(&out[lbl], 1.0f);
}

// Multiset hashes: blocks 0..255 -> row hash (coalesced), 256..511 -> col hash
// (strided, L2-resident). Optionally clears the big table (layer 2 reuse).
__global__ void k_hash(int clear_tbl) {
    int b = blockIdx.x, t = threadIdx.x;
    if (clear_tbl) {                                    // 512*256 = TBL exactly
        int idx = b * 256 + t;
        d_tkey[idx] = EMPTYK;
        d_tmin[idx] = POSINF;
    }
    unsigned long long h;
    if (b < NN) h = mix64((unsigned long long)(unsigned)d_labels[b * NN + t]);
    else        h = mix64((unsigned long long)(unsigned)d_labels[t * NN + (b - NN)]);
    // block sum reduce: warp shfl + smem
    #pragma unroll
    for (int o = 16; o > 0; o >>= 1) h += __shfl_down_sync(0xFFFFFFFFu, h, o);
    __shared__ unsigned long long ws[8];
    int lane = t & 31, w = t >> 5;
    if (lane == 0) ws[w] = h;
    __syncthreads();
    if (t == 0) {
        unsigned long long s = ws[0];
        #pragma unroll
        for (int q = 1; q < 8; q++) s += ws[q];
        d_hashRC[b] = s;
    }
}

// rid[i] = min i' with equal row multiset hash; same for cols. One block.
__global__ void k_dedupe() {
    __shared__ unsigned long long sh[2 * NN];
    int t = threadIdx.x;                                // 512 threads
    sh[t] = d_hashRC[t];
    __syncthreads();
    int idx = t & 255;
    int base = (t >> 8) << 8;
    unsigned long long my = sh[t];
    int c = 0;
    while (sh[base + c] != my) c++;                     // c <= idx always terminates
    if (t < NN) d_rid[idx] = c;
    else        d_cid[idx] = c;
}

// Insert packed key (label<<16 | rid<<8 | cid); record slot, min row-major pos.
__global__ void k_insert() {
    int m = blockIdx.x * 256 + threadIdx.x;
    int i = m >> 8, j = m & 255;
    unsigned int key = ((unsigned)d_labels[m] << 16) | ((unsigned)d_rid[i] << 8) | (unsigned)d_cid[j];
    unsigned long long k64 = (unsigned long long)key;
    unsigned int h = (key * 2654435761u) >> 15;         // -> [0, 2^17)
    int slot;
    while (true) {
        unsigned long long cur = d_tkey[h];
        if (cur == k64) { slot = (int)h; break; }
        if (cur == EMPTYK) {
            unsigned long long old = atomicCAS(&d_tkey[h], EMPTYK, k64);
            if (old == EMPTYK || old == k64) { slot = (int)h; break; }
        }
        h = (h + 1) & (TBL - 1);
    }
    d_slot[m] = slot;
    if (m < d_tmin[slot]) atomicMin(&d_tmin[slot], m);
}

// Per-block exclusive scan of first-occurrence indicator + block sums (shfl scan).
__global__ void k_scanA() {
    __shared__ int ws[8];
    int b = blockIdx.x, t = threadIdx.x, m = b * 256 + t;
    int f = (d_tmin[d_slot[m]] == m) ? 1 : 0;
    int lane = t & 31, w = t >> 5;
    int incl = f;
    #pragma unroll
    for (int o = 1; o < 32; o <<= 1) {
        int v = __shfl_up_sync(0xFFFFFFFFu, incl, o);
        if (lane >= o) incl += v;
    }
    if (lane == 31) ws[w] = incl;
    __syncthreads();
    if (w == 0 && lane < 8) {
        int v = ws[lane];
        int s = v;
        #pragma unroll
        for (int o = 1; o < 8; o <<= 1) {
            int u = __shfl_up_sync(0xFFu, s, o);
            if (lane >= o) s += u;
        }
        ws[lane] = s - v;                               // exclusive warp offsets
    }
    __syncthreads();
    int excl = incl - f + ws[w];
    d_preL[m] = excl;
    if (t == 255) d_bsum[b] = excl + f;
}

__global__ void k_scanB() {
    __shared__ int ws[8];
    int t = threadIdx.x;
    int v0 = d_bsum[t];
    int lane = t & 31, w = t >> 5;
    int incl = v0;
    #pragma unroll
    for (int o = 1; o < 32; o <<= 1) {
        int v = __shfl_up_sync(0xFFFFFFFFu, incl, o);
        if (lane >= o) incl += v;
    }
    if (lane == 31) ws[w] = incl;
    __syncthreads();
    if (w == 0 && lane < 8) {
        int v = ws[lane];
        int s = v;
        #pragma unroll
        for (int o = 1; o < 8; o <<= 1) {
            int u = __shfl_up_sync(0xFFu, s, o);
            if (lane >= o) s += u;
        }
        ws[lane] = s - v;
    }
    __syncthreads();
    d_boff[t] = incl - v0 + ws[w];
}

// New label = rank of key = #first-occurrences strictly before its first position.
__global__ void k_final(float* out, int layer) {
    int m = blockIdx.x * 256 + threadIdx.x;
    int fp = d_tmin[d_slot[m]];
    int lbl = d_preL[fp] + d_boff[fp >> 8];
    d_labels[m] = lbl;
    atomicAdd(&out[layer * MM + lbl], 1.0f);
}

// ---------------- launch ----------------
extern "C" void kernel_launch(void* const* d_in, const int* in_sizes, int n_in,
                              void* d_out, int out_size) {
    // Fixed instance: N=256, E=8192, C=16. x is the smaller buffer.
    const int* x;
    const int* ei;
    if (in_sizes[0] <= in_sizes[1]) {
        x  = (const int*)d_in[0];
        ei = (const int*)d_in[1];
    } else {
        ei = (const int*)d_in[0];
        x  = (const int*)d_in[1];
    }
    float* out = (float*)d_out;

    k_init<<<768, 256>>>(out);
    k_edges<<<EE / 256, 256>>>(ei);
    k_minpos0<<<256, 256>>>(x);
    k_rank0<<<1, 1024>>>();
    k_label0<<<256, 256>>>(x, out);

    for (int layer = 1; layer <= 2; layer++) {
        k_hash<<<512, 256>>>(layer == 2 ? 1 : 0);
        k_dedupe<<<1, 512>>>();
        k_insert<<<256, 256>>>();
        k_scanA<<<256, 256>>>();
        k_scanB<<<1, 256>>>();
        k_final<<<256, 256>>>(out, layer);
    }
}